// round 1
// baseline (speedup 1.0000x reference)
#include <cuda_runtime.h>
#include <cuda_bf16.h>

// AttentionMV: B=T=1024, E=128
//   u   = tanh(m[b] @ W[b] + bias)          (T,E)   per batch
//   pre = v^T @ u                           (E,E)   contraction over time
//   alpha = softmax(pre, axis=-1)
//   out[b,:] = s[b]^T @ alpha, s[b,e] = sum_t m[b,t,e]
// Fully fused: one CTA per batch, u stays in SMEM, pre stays in registers.

constexpr int Bn = 1024;
constexpr int Tn = 1024;
constexpr int En = 128;
constexpr int TT = 64;          // time tile
constexpr int NTHREADS = 256;   // 16 x 16 thread grid

constexpr int SMEM_FLOATS = En * En + 3 * TT * En + 2 * En;
constexpr size_t SMEM_BYTES = SMEM_FLOATS * sizeof(float);

__device__ __forceinline__ float fast_tanh(float x) {
    // tanh(x) = 1 - 2/(exp(2x)+1); saturates correctly for |x| large.
    float e = __expf(2.0f * x);
    return 1.0f - __fdividef(2.0f, e + 1.0f);
}

__global__ __launch_bounds__(NTHREADS, 1)
void attn_mv_kernel(const float* __restrict__ gm, const float* __restrict__ gv,
                    const float* __restrict__ gW, const float* __restrict__ gb,
                    float* __restrict__ gout)
{
    extern __shared__ float smem[];
    float* Ws   = smem;              // [128][128], Ws[k*128 + f] = W[b,k,f]
    float* ms   = Ws + En * En;      // [TT][128] m tile
    float* us   = ms + TT * En;      // [TT][128] u tile
    float* vs   = us + TT * En;      // [TT][128] v tile
    float* ssum = vs + TT * En;      // [128] column sums of m[b]
    float* red  = ssum + En;         // [128] output reduction

    const int bb  = blockIdx.x;
    const int tid = threadIdx.x;
    const int tx  = tid & 15;        // f-block (8 cols)
    const int ty  = tid >> 4;        // e-block (8 rows) / t-block (4 rows)

    const float* Wb = gW + (size_t)bb * En * En;
    const float* mb = gm + (size_t)bb * Tn * En;

    // Load W[b] into SMEM (row-major, k = contraction index of GEMM1)
    #pragma unroll
    for (int i = 0; i < (En * En) / (NTHREADS * 4); i++) {
        int off = (i * NTHREADS + tid) * 4;
        *reinterpret_cast<float4*>(Ws + off) =
            *reinterpret_cast<const float4*>(Wb + off);
    }
    if (tid < En) { ssum[tid] = 0.0f; red[tid] = 0.0f; }

    // pre[e][f] accumulator, e = ty*8+i, f = tx*8+j
    float pre[8][8];
    #pragma unroll
    for (int i = 0; i < 8; i++)
        #pragma unroll
        for (int j = 0; j < 8; j++) pre[i][j] = 0.0f;

    for (int t0 = 0; t0 < Tn; t0 += TT) {
        __syncthreads();  // previous iteration done with ms/us/vs (and W loaded)

        // Load m tile and v tile
        #pragma unroll
        for (int i = 0; i < (TT * En) / (NTHREADS * 4); i++) {
            int off = (i * NTHREADS + tid) * 4;
            *reinterpret_cast<float4*>(ms + off) =
                *reinterpret_cast<const float4*>(mb + (size_t)t0 * En + off);
            *reinterpret_cast<float4*>(vs + off) =
                *reinterpret_cast<const float4*>(gv + (size_t)t0 * En + off);
        }
        __syncthreads();

        // Column sums of m tile (for the final GEMV)
        if (tid < En) {
            float acc = 0.0f;
            #pragma unroll 16
            for (int t = 0; t < TT; t++) acc += ms[t * En + tid];
            ssum[tid] += acc;
        }

        // ---- GEMM1: ua[t'][f] = bias + m_tile @ W ;  t' = ty*4..+4, f = tx*8..+8
        float ua[4][8];
        #pragma unroll
        for (int i = 0; i < 4; i++) {
            int tg = t0 + ty * 4 + i;  // bias indexed by global time row (T==B)
            float4 b0 = *reinterpret_cast<const float4*>(gb + tg * En + tx * 8);
            float4 b1 = *reinterpret_cast<const float4*>(gb + tg * En + tx * 8 + 4);
            ua[i][0] = b0.x; ua[i][1] = b0.y; ua[i][2] = b0.z; ua[i][3] = b0.w;
            ua[i][4] = b1.x; ua[i][5] = b1.y; ua[i][6] = b1.z; ua[i][7] = b1.w;
        }
        #pragma unroll 4
        for (int k = 0; k < En; k++) {
            float a[4];
            #pragma unroll
            for (int i = 0; i < 4; i++) a[i] = ms[(ty * 4 + i) * En + k];
            float4 w0 = *reinterpret_cast<const float4*>(Ws + k * En + tx * 8);
            float4 w1 = *reinterpret_cast<const float4*>(Ws + k * En + tx * 8 + 4);
            float wv[8] = {w0.x, w0.y, w0.z, w0.w, w1.x, w1.y, w1.z, w1.w};
            #pragma unroll
            for (int i = 0; i < 4; i++)
                #pragma unroll
                for (int j = 0; j < 8; j++)
                    ua[i][j] = fmaf(a[i], wv[j], ua[i][j]);
        }
        // tanh + store u tile
        #pragma unroll
        for (int i = 0; i < 4; i++) {
            float4 o0, o1;
            o0.x = fast_tanh(ua[i][0]); o0.y = fast_tanh(ua[i][1]);
            o0.z = fast_tanh(ua[i][2]); o0.w = fast_tanh(ua[i][3]);
            o1.x = fast_tanh(ua[i][4]); o1.y = fast_tanh(ua[i][5]);
            o1.z = fast_tanh(ua[i][6]); o1.w = fast_tanh(ua[i][7]);
            *reinterpret_cast<float4*>(us + (ty * 4 + i) * En + tx * 8)     = o0;
            *reinterpret_cast<float4*>(us + (ty * 4 + i) * En + tx * 8 + 4) = o1;
        }
        __syncthreads();

        // ---- GEMM2: pre[e][f] += sum_t v[t][e] * u[t][f]
        #pragma unroll 2
        for (int t = 0; t < TT; t++) {
            float4 e0 = *reinterpret_cast<const float4*>(vs + t * En + ty * 8);
            float4 e1 = *reinterpret_cast<const float4*>(vs + t * En + ty * 8 + 4);
            float4 f0 = *reinterpret_cast<const float4*>(us + t * En + tx * 8);
            float4 f1 = *reinterpret_cast<const float4*>(us + t * En + tx * 8 + 4);
            float ev[8] = {e0.x, e0.y, e0.z, e0.w, e1.x, e1.y, e1.z, e1.w};
            float fv[8] = {f0.x, f0.y, f0.z, f0.w, f1.x, f1.y, f1.z, f1.w};
            #pragma unroll
            for (int i = 0; i < 8; i++)
                #pragma unroll
                for (int j = 0; j < 8; j++)
                    pre[i][j] = fmaf(ev[i], fv[j], pre[i][j]);
        }
    }
    __syncthreads();

    // ---- Softmax over f (axis=-1) per row e, weighted by s[e], reduce over e.
    // Row e's 128 entries live across the 16 tx lanes (a half-warp; width-16 shuffles).
    float acc[8];
    #pragma unroll
    for (int j = 0; j < 8; j++) acc[j] = 0.0f;

    #pragma unroll
    for (int i = 0; i < 8; i++) {
        float mx = pre[i][0];
        #pragma unroll
        for (int j = 1; j < 8; j++) mx = fmaxf(mx, pre[i][j]);
        #pragma unroll
        for (int off = 8; off >= 1; off >>= 1)
            mx = fmaxf(mx, __shfl_xor_sync(0xffffffffu, mx, off, 16));
        float sum = 0.0f;
        float ex[8];
        #pragma unroll
        for (int j = 0; j < 8; j++) { ex[j] = __expf(pre[i][j] - mx); sum += ex[j]; }
        #pragma unroll
        for (int off = 8; off >= 1; off >>= 1)
            sum += __shfl_xor_sync(0xffffffffu, sum, off, 16);
        float coef = ssum[ty * 8 + i] * __fdividef(1.0f, sum);
        #pragma unroll
        for (int j = 0; j < 8; j++) acc[j] = fmaf(coef, ex[j], acc[j]);
    }
    #pragma unroll
    for (int j = 0; j < 8; j++) atomicAdd(&red[tx * 8 + j], acc[j]);
    __syncthreads();

    if (tid < En) gout[(size_t)bb * En + tid] = red[tid];
}

extern "C" void kernel_launch(void* const* d_in, const int* in_sizes, int n_in,
                              void* d_out, int out_size) {
    const float* m = (const float*)d_in[0];
    const float* v = (const float*)d_in[1];
    const float* W = (const float*)d_in[2];
    const float* b = (const float*)d_in[3];
    float* out = (float*)d_out;

    cudaFuncSetAttribute(attn_mv_kernel,
                         cudaFuncAttributeMaxDynamicSharedMemorySize,
                         (int)SMEM_BYTES);
    attn_mv_kernel<<<Bn, NTHREADS, SMEM_BYTES>>>(m, v, W, b, out);
}

// round 3
// speedup vs baseline: 1.1281x; 1.1281x over previous
#include <cuda_runtime.h>
#include <cstdint>

// AttentionMV: B=T=1024, E=128
//   u   = tanh(m[b] @ W[b] + bias)       (T,E)
//   pre = v^T @ u                        (E,E)
//   alpha = softmax(pre, axis=-1)
//   out[b] = colsum(m[b]) @ alpha
// Fused, one CTA per batch. FFMA2 (fma.rn.f32x2) inner loops, conflict-free
// lane mapping (thread owns cols lane*4..+4), 2 CTAs/SM.

constexpr int Bn = 1024;
constexpr int Tn = 1024;
constexpr int En = 128;
constexpr int TT = 32;          // time tile
constexpr int NTHREADS = 256;   // 8 warps

constexpr int SMEM_FLOATS = En * En + 2 * TT * En + 2 * En;
constexpr size_t SMEM_BYTES = SMEM_FLOATS * sizeof(float);

typedef unsigned long long u64;

__device__ __forceinline__ u64 ffma2(u64 a, u64 b, u64 c) {
    u64 d;
    asm("fma.rn.f32x2 %0, %1, %2, %3;" : "=l"(d) : "l"(a), "l"(b), "l"(c));
    return d;
}
__device__ __forceinline__ u64 pack2(float x) {
    u64 d;
    unsigned xu = __float_as_uint(x);
    asm("mov.b64 %0, {%1, %1};" : "=l"(d) : "r"(xu));
    return d;
}
__device__ __forceinline__ void unpack2(u64 v, float& lo, float& hi) {
    unsigned a, b;
    asm("mov.b64 {%0, %1}, %2;" : "=r"(a), "=r"(b) : "l"(v));
    lo = __uint_as_float(a);
    hi = __uint_as_float(b);
}

__device__ __forceinline__ float fast_tanh(float x) {
    float e = __expf(2.0f * x);
    return 1.0f - __fdividef(2.0f, e + 1.0f);
}

__global__ __launch_bounds__(NTHREADS, 2)
void attn_mv_kernel(const float* __restrict__ gm, const float* __restrict__ gv,
                    const float* __restrict__ gW, const float* __restrict__ gb,
                    float* __restrict__ gout)
{
    extern __shared__ float smem[];
    float* Ws   = smem;              // [128][128]
    float* ms   = Ws + En * En;      // [TT][128]
    float* us   = ms + TT * En;      // [TT][128]
    float* ssum = us + TT * En;      // [128] column sums of m[b]
    float* red  = ssum + En;         // [128] output reduction

    const int bb   = blockIdx.x;
    const int tid  = threadIdx.x;
    const int lane = tid & 31;       // owns cols lane*4..lane*4+3
    const int w    = tid >> 5;       // warp 0..7

    const float* Wb = gW + (size_t)bb * En * En;
    const float* mb = gm + (size_t)bb * Tn * En;

    // Load W[b] into SMEM
    #pragma unroll
    for (int i = 0; i < (En * En) / (NTHREADS * 4); i++) {
        int off = (i * NTHREADS + tid) * 4;
        *reinterpret_cast<float4*>(Ws + off) =
            *reinterpret_cast<const float4*>(Wb + off);
    }
    if (tid < En) { ssum[tid] = 0.0f; red[tid] = 0.0f; }

    // pre accumulators: warp w owns e-rows w*16..+15; thread owns f=lane*4..+3
    u64 pre2[16][2];
    #pragma unroll
    for (int i = 0; i < 16; i++) { pre2[i][0] = 0ull; pre2[i][1] = 0ull; }

    for (int t0 = 0; t0 < Tn; t0 += TT) {
        __syncthreads();  // A: prev iter done with ms/us

        // Load m tile (TT*128 floats; 4 float4 per thread, coalesced)
        #pragma unroll
        for (int i = 0; i < (TT * En) / (NTHREADS * 4); i++) {
            int off = (i * NTHREADS + tid) * 4;
            *reinterpret_cast<float4*>(ms + off) =
                *reinterpret_cast<const float4*>(mb + (size_t)t0 * En + off);
        }
        __syncthreads();  // B

        // Column sums of m tile (lanes consecutive -> conflict-free)
        if (tid < En) {
            float acc = 0.0f;
            #pragma unroll
            for (int t = 0; t < TT; t++) acc += ms[t * En + tid];
            ssum[tid] += acc;
        }

        // ---- GEMM1: warp w computes u rows t' = w*4..+3, cols lane*4..+3
        u64 ua[4][2];
        #pragma unroll
        for (int i = 0; i < 4; i++) {
            int tg = t0 + w * 4 + i;   // bias indexed by global time (T==B)
            const float* bp = gb + (size_t)tg * En + lane * 4;
            ua[i][0] = *reinterpret_cast<const u64*>(bp);
            ua[i][1] = *reinterpret_cast<const u64*>(bp + 2);
        }
        #pragma unroll 4
        for (int k = 0; k < En; k += 4) {
            u64 ap[4][4];
            #pragma unroll
            for (int i = 0; i < 4; i++) {
                float4 t4 = *reinterpret_cast<const float4*>(ms + (w * 4 + i) * En + k);
                ap[i][0] = pack2(t4.x); ap[i][1] = pack2(t4.y);
                ap[i][2] = pack2(t4.z); ap[i][3] = pack2(t4.w);
            }
            #pragma unroll
            for (int kk = 0; kk < 4; kk++) {
                ulonglong2 wv = *reinterpret_cast<const ulonglong2*>(
                    Ws + (k + kk) * En + lane * 4);
                #pragma unroll
                for (int i = 0; i < 4; i++) {
                    ua[i][0] = ffma2(ap[i][kk], wv.x, ua[i][0]);
                    ua[i][1] = ffma2(ap[i][kk], wv.y, ua[i][1]);
                }
            }
        }
        // tanh + store u tile
        #pragma unroll
        for (int i = 0; i < 4; i++) {
            float x0, x1, x2, x3;
            unpack2(ua[i][0], x0, x1);
            unpack2(ua[i][1], x2, x3);
            float4 o;
            o.x = fast_tanh(x0); o.y = fast_tanh(x1);
            o.z = fast_tanh(x2); o.w = fast_tanh(x3);
            *reinterpret_cast<float4*>(us + (w * 4 + i) * En + lane * 4) = o;
        }
        __syncthreads();  // C: u tile ready

        // ---- GEMM2: pre[e][f] += v[t][e] * u[t][f], e = w*16..+15
        const float* vbase = gv + (size_t)t0 * En + w * 16;
        #pragma unroll 2
        for (int t = 0; t < TT; t++) {
            ulonglong2 u2 = *reinterpret_cast<const ulonglong2*>(
                us + t * En + lane * 4);
            float4 v0 = __ldg(reinterpret_cast<const float4*>(vbase + t * En + 0));
            float4 v1 = __ldg(reinterpret_cast<const float4*>(vbase + t * En + 4));
            float4 v2 = __ldg(reinterpret_cast<const float4*>(vbase + t * En + 8));
            float4 v3 = __ldg(reinterpret_cast<const float4*>(vbase + t * En + 12));
            float vv[16] = {v0.x, v0.y, v0.z, v0.w, v1.x, v1.y, v1.z, v1.w,
                            v2.x, v2.y, v2.z, v2.w, v3.x, v3.y, v3.z, v3.w};
            #pragma unroll
            for (int i = 0; i < 16; i++) {
                u64 vp = pack2(vv[i]);
                pre2[i][0] = ffma2(vp, u2.x, pre2[i][0]);
                pre2[i][1] = ffma2(vp, u2.y, pre2[i][1]);
            }
        }
    }
    __syncthreads();

    // ---- Softmax over f per row e, weighted by ssum[e], reduced over e.
    // Row e = w*16+i spans the full warp (32 lanes x 4 cols).
    float acc[4] = {0.0f, 0.0f, 0.0f, 0.0f};

    #pragma unroll
    for (int i = 0; i < 16; i++) {
        float p[4];
        unpack2(pre2[i][0], p[0], p[1]);
        unpack2(pre2[i][1], p[2], p[3]);
        float mx = fmaxf(fmaxf(p[0], p[1]), fmaxf(p[2], p[3]));
        #pragma unroll
        for (int off = 16; off >= 1; off >>= 1)
            mx = fmaxf(mx, __shfl_xor_sync(0xffffffffu, mx, off));
        float ex[4];
        float sum = 0.0f;
        #pragma unroll
        for (int j = 0; j < 4; j++) { ex[j] = __expf(p[j] - mx); sum += ex[j]; }
        #pragma unroll
        for (int off = 16; off >= 1; off >>= 1)
            sum += __shfl_xor_sync(0xffffffffu, sum, off);
        float coef = ssum[w * 16 + i] * __fdividef(1.0f, sum);
        #pragma unroll
        for (int j = 0; j < 4; j++) acc[j] = fmaf(coef, ex[j], acc[j]);
    }
    #pragma unroll
    for (int j = 0; j < 4; j++) atomicAdd(&red[lane * 4 + j], acc[j]);
    __syncthreads();

    if (tid < En) gout[(size_t)bb * En + tid] = red[tid];
}

extern "C" void kernel_launch(void* const* d_in, const int* in_sizes, int n_in,
                              void* d_out, int out_size) {
    const float* m = (const float*)d_in[0];
    const float* v = (const float*)d_in[1];
    const float* W = (const float*)d_in[2];
    const float* b = (const float*)d_in[3];
    float* out = (float*)d_out;

    cudaFuncSetAttribute(attn_mv_kernel,
                         cudaFuncAttributeMaxDynamicSharedMemorySize,
                         (int)SMEM_BYTES);
    attn_mv_kernel<<<Bn, NTHREADS, SMEM_BYTES>>>(m, v, W, b, out);
}